// round 12
// baseline (speedup 1.0000x reference)
#include <cuda_runtime.h>

// Problem constants
#define Bq 4
#define Hq 256
#define Wq 256
#define Zq 64
#define ITER 8
#define EPS 1e-6

constexpr int N    = Bq * Hq * Wq * Zq;   // 16,777,216
constexpr int SAMP = Hq * Wq * Zq;        // 4,194,304
#define NT 256
constexpr int GRID = 592;                 // 148 SMs x 4 blocks co-resident
constexpr int SBLK = GRID / Bq;           // 148 blocks per sample
constexpr int TPS  = SAMP / (NT * 4);     // 4096 tiles per sample
constexpr int WZ   = Wq * Zq;

// Scratch (device globals; allocation forbidden). Write-once versioning.
__device__ float g_p[ITER][N];   // p_0..p_7 (r_k = p_k - beta_k p_{k-1})

__device__ double   g_rho[ITER + 1][Bq];
__device__ double   g_eta[ITER][Bq];
__device__ double   g_tau[ITER][Bq];
__device__ double   g_om [ITER][Bq];
__device__ double   g_loss;
__device__ unsigned g_max;

__device__ unsigned g_bar_count;
__device__ unsigned g_bar_gen;

// ---------------------------------------------------------------------------
// helpers
// ---------------------------------------------------------------------------

__device__ __forceinline__ float4 ld4(const float* __restrict__ p) {
    return *reinterpret_cast<const float4*>(p);
}
__device__ __forceinline__ float4 ld4cs(const float* __restrict__ p) {
    return __ldcs(reinterpret_cast<const float4*>(p));
}
__device__ __forceinline__ void st4(float* __restrict__ p, float4 v) {
    *reinterpret_cast<float4*>(p) = v;
}
__device__ __forceinline__ float dot4(float4 a, float4 b) {
    return a.x * b.x + a.y * b.y + a.z * b.z + a.w * b.w;
}
__device__ __forceinline__ float4 add4(float4 a, float4 b) {
    return make_float4(a.x + b.x, a.y + b.y, a.z + b.z, a.w + b.w);
}

// z-shift helpers: quad value at z-1 / z+1 / z-2 / z+2, zero Dirichlet.
// 16 lanes tile one z-line (z=0..63); lane-boundary shuffles are masked by z0.
// MUST be called by all lanes (shuffles inside).
__device__ __forceinline__ float4 zsm(float4 q, int z0) {      // z-1
    float t = __shfl_up_sync(0xffffffffu, q.w, 1);
    return make_float4(z0 == 0 ? 0.f : t, q.x, q.y, q.z);
}
__device__ __forceinline__ float4 zsp(float4 q, int z0) {      // z+1
    float t = __shfl_down_sync(0xffffffffu, q.x, 1);
    return make_float4(q.y, q.z, q.w, z0 == 60 ? 0.f : t);
}
__device__ __forceinline__ float4 zsm2(float4 q, int z0) {     // z-2
    float tz = __shfl_up_sync(0xffffffffu, q.z, 1);
    float tw = __shfl_up_sync(0xffffffffu, q.w, 1);
    bool m = (z0 == 0);
    return make_float4(m ? 0.f : tz, m ? 0.f : tw, q.x, q.y);
}
__device__ __forceinline__ float4 zsp2(float4 q, int z0) {     // z+2
    float tx = __shfl_down_sync(0xffffffffu, q.x, 1);
    float ty = __shfl_down_sync(0xffffffffu, q.y, 1);
    bool m = (z0 == 60);
    return make_float4(q.z, q.w, m ? 0.f : tx, m ? 0.f : ty);
}

// 7-pt Laplacian (used by P0/P1/final)
__device__ __forceinline__ float4 lap(float4 c, float4 xm, float4 xp,
                                      float4 ym, float4 yp, int z0) {
    float4 s = add4(add4(add4(xm, xp), add4(ym, yp)),
                    add4(zsm(c, z0), zsp(c, z0)));
    return make_float4(6.f * c.x - s.x, 6.f * c.y - s.y,
                       6.f * c.z - s.z, 6.f * c.w - s.w);
}

__device__ __forceinline__ void block_reduce_add(float val, double* target) {
    __syncthreads();
    #pragma unroll
    for (int o = 16; o; o >>= 1)
        val += __shfl_xor_sync(0xffffffffu, val, o);
    __shared__ double sh[NT / 32];
    int lane = threadIdx.x & 31, wid = threadIdx.x >> 5;
    if (lane == 0) sh[wid] = (double)val;
    __syncthreads();
    if (threadIdx.x == 0) {
        double s = 0.0;
        #pragma unroll
        for (int k = 0; k < NT / 32; ++k) s += sh[k];
        atomicAdd(target, s);
    }
}

__device__ __forceinline__ void block_reduce4(float v0, float v1, float v2,
                                              float v3, double* t0, double* t1,
                                              double* t2, double* t3) {
    __syncthreads();
    #pragma unroll
    for (int o = 16; o; o >>= 1) {
        v0 += __shfl_xor_sync(0xffffffffu, v0, o);
        v1 += __shfl_xor_sync(0xffffffffu, v1, o);
        v2 += __shfl_xor_sync(0xffffffffu, v2, o);
        v3 += __shfl_xor_sync(0xffffffffu, v3, o);
    }
    __shared__ double sh[4][NT / 32];
    int lane = threadIdx.x & 31, wid = threadIdx.x >> 5;
    if (lane == 0) {
        sh[0][wid] = v0; sh[1][wid] = v1; sh[2][wid] = v2; sh[3][wid] = v3;
    }
    __syncthreads();
    if (threadIdx.x < 4) {
        double s = 0.0;
        #pragma unroll
        for (int k = 0; k < NT / 32; ++k) s += sh[threadIdx.x][k];
        double* tgt = (threadIdx.x == 0) ? t0 : (threadIdx.x == 1) ? t1
                    : (threadIdx.x == 2) ? t2 : t3;
        atomicAdd(tgt, s);
    }
}

__device__ __forceinline__ void block_reduce_max(float val, unsigned* target) {
    __syncthreads();
    #pragma unroll
    for (int o = 16; o; o >>= 1)
        val = fmaxf(val, __shfl_xor_sync(0xffffffffu, val, o));
    __shared__ float shm[NT / 32];
    int lane = threadIdx.x & 31, wid = threadIdx.x >> 5;
    if (lane == 0) shm[wid] = val;
    __syncthreads();
    if (threadIdx.x == 0) {
        float m = 0.f;
        #pragma unroll
        for (int k = 0; k < NT / 32; ++k) m = fmaxf(m, shm[k]);
        atomicMax(target, __float_as_uint(m));
    }
}

__device__ __forceinline__ void grid_sync() {
    __syncthreads();
    if (threadIdx.x == 0) {
        unsigned my = *(volatile unsigned*)&g_bar_gen;
        __threadfence();
        if (atomicAdd(&g_bar_count, 1) == GRID - 1) {
            g_bar_count = 0;
            __threadfence();
            atomicAdd(&g_bar_gen, 1);
        } else {
            while (*(volatile unsigned*)&g_bar_gen == my) __nanosleep(64);
        }
        __threadfence();
    }
    __syncthreads();
}

__device__ __forceinline__ void decode(int sb, int t, int& i, int& z0,
                                       int& wi, int& h) {
    i  = (sb << 22) + (t * NT + (int)threadIdx.x) * 4;
    z0 = i & 63;
    wi = (i >> 6) & 255;
    h  = (i >> 14) & 255;
}

// alpha_j and beta_{j+1} from dots of iteration j (double, fixed op order).
__device__ __forceinline__ void scal_ab(int j, int sb, double& al, double& bt) {
    double r = __ldcg(&g_rho[j][sb]);
    double e = __ldcg(&g_eta[j][sb]);
    double t = __ldcg(&g_tau[j][sb]);
    double o = __ldcg(&g_om [j][sb]);
    al = r / (e + EPS);
    double rr = r - 2.0 * al * t + al * al * o;
    bt = rr / (r + EPS);
}

// ---------------------------------------------------------------------------
// kernels
// ---------------------------------------------------------------------------

__global__ void k_zero() {
    int t = threadIdx.x;
    if (t < (ITER + 1) * Bq) ((double*)g_rho)[t] = 0.0;
    if (t < ITER * Bq) {
        ((double*)g_eta)[t] = 0.0;
        ((double*)g_tau)[t] = 0.0;
        ((double*)g_om)[t]  = 0.0;
    }
    if (t == 0) { g_loss = 0.0; g_max = 0u; }
}

__global__ void __launch_bounds__(NT, 4)
k_cg(const float* __restrict__ x0, const float* __restrict__ bin,
     const float* __restrict__ ref, float* __restrict__ out) {
    const int sb   = blockIdx.x & 3;
    const int sblk = blockIdx.x >> 2;
    const float4 Zv = make_float4(0.f, 0.f, 0.f, 0.f);
    __shared__ float s_a, s_bk, s_bp;

    // ---- P0 (asc): p0 = r0 = b - A x0 ; rho0 ----
    {
        float acc = 0.f;
        for (int t = sblk; t < TPS; t += SBLK) {
            int i, z0, wi, h; decode(sb, t, i, z0, wi, h);
            bool w1 = wi > 0, e1 = wi < Wq - 1, n1 = h > 0, s1 = h < Hq - 1;
            float4 xc = ld4(x0 + i);
            float4 xw = w1 ? ld4(x0 + i - Zq) : Zv;
            float4 xe = e1 ? ld4(x0 + i + Zq) : Zv;
            float4 xn = n1 ? ld4(x0 + i - WZ) : Zv;
            float4 xs = s1 ? ld4(x0 + i + WZ) : Zv;
            float4 ax = lap(xc, xw, xe, xn, xs, z0);
            float4 bb = ld4cs(bin + i);
            float4 r0 = make_float4(bb.x - ax.x, bb.y - ax.y,
                                    bb.z - ax.z, bb.w - ax.w);
            st4(g_p[0] + i, r0);
            acc += dot4(r0, r0);
        }
        block_reduce_add(acc, &g_rho[0][sb]);
    }
    grid_sync();

    // ---- P1 (desc): w0 = A p0 ; eta0 = tau0 = p0.w0 ; om0 = w0.w0 ----
    {
        float accE = 0.f, accO = 0.f;
        for (int t = sblk; t < TPS; t += SBLK) {
            int tt = TPS - 1 - t;
            int i, z0, wi, h; decode(sb, tt, i, z0, wi, h);
            bool w1 = wi > 0, e1 = wi < Wq - 1, n1 = h > 0, s1 = h < Hq - 1;
            const float* p0 = g_p[0];
            float4 pc  = ld4(p0 + i);
            float4 pw  = w1 ? ld4(p0 + i - Zq) : Zv;
            float4 pe  = e1 ? ld4(p0 + i + Zq) : Zv;
            float4 pn4 = n1 ? ld4(p0 + i - WZ) : Zv;
            float4 ps4 = s1 ? ld4(p0 + i + WZ) : Zv;
            float4 w = lap(pc, pw, pe, pn4, ps4, z0);
            accE += dot4(pc, w);
            accO += dot4(w, w);
        }
        block_reduce4(accE, accE, accO, 0.f,
                      &g_eta[0][sb], &g_tau[0][sb], &g_om[0][sb], &g_loss);
    }
    grid_sync();

    // ---- fused phases k = 1..7: direct 25-pt A^2, p-only state ----
    for (int k = 1; k < ITER; ++k) {
        if (threadIdx.x == 0) {
            double al, bk;
            scal_ab(k - 1, sb, al, bk);
            s_a = (float)al; s_bk = (float)bk;
            if (k >= 2) {
                double ap_, bp_;
                scal_ab(k - 2, sb, ap_, bp_);
                s_bp = (float)bp_;
            }
        }
        __syncthreads();
        const float al = s_a, bk = s_bk, bp = (k >= 2) ? s_bp : 0.f;
        const float* pp = g_p[k - 1];
        const float* qq = (k >= 2) ? g_p[k - 2] : nullptr;
        float* pout = g_p[k];
        const bool rev = !(k & 1);
        float accR = 0.f, accE = 0.f, accT = 0.f, accO = 0.f;

        for (int t = sblk; t < TPS; t += SBLK) {
            int tt = rev ? TPS - 1 - t : t;
            int i, z0, wi, h; decode(sb, tt, i, z0, wi, h);
            bool w1 = wi > 0,  e1 = wi < Wq - 1;
            bool n1 = h  > 0,  s1 = h  < Hq - 1;
            bool w2 = wi > 1,  e2 = wi < Wq - 2;
            bool n2 = h  > 1,  s2 = h  < Hq - 2;

            // ---- loads (13 quads of p) ----
            float4 pc  = ld4(pp + i);
            float4 pw  = w1 ? ld4(pp + i - Zq) : Zv;
            float4 pe  = e1 ? ld4(pp + i + Zq) : Zv;
            float4 pn4 = n1 ? ld4(pp + i - WZ) : Zv;
            float4 ps4 = s1 ? ld4(pp + i + WZ) : Zv;

            // first-neighbor sum, 7-pt A p
            float4 S1 = add4(add4(add4(pw, pe), add4(pn4, ps4)),
                             add4(zsm(pc, z0), zsp(pc, z0)));
            float4 ap = make_float4(6.f * pc.x - S1.x, 6.f * pc.y - S1.y,
                                    6.f * pc.z - S1.z, 6.f * pc.w - S1.w);

            // axis +/-2 terms (folded as loaded)
            float4 ax2;
            {
                float4 pww = w2 ? ld4(pp + i - 2 * Zq) : Zv;
                float4 pee = e2 ? ld4(pp + i + 2 * Zq) : Zv;
                float4 pnn = n2 ? ld4(pp + i - 2 * WZ) : Zv;
                float4 pss = s2 ? ld4(pp + i + 2 * WZ) : Zv;
                ax2 = add4(add4(add4(pww, pee), add4(pnn, pss)),
                           add4(zsm2(pc, z0), zsp2(pc, z0)));
            }

            // planar diagonal terms
            float4 diag;
            {
                float4 pnw = (w1 && n1) ? ld4(pp + i - Zq - WZ) : Zv;
                float4 pne = (e1 && n1) ? ld4(pp + i + Zq - WZ) : Zv;
                float4 psw = (w1 && s1) ? ld4(pp + i - Zq + WZ) : Zv;
                float4 pse = (e1 && s1) ? ld4(pp + i + Zq + WZ) : Zv;
                diag = add4(add4(pnw, pne), add4(psw, pse));
                diag = add4(diag, add4(zsm(pw, z0), zsp(pw, z0)));
                diag = add4(diag, add4(zsm(pe, z0), zsp(pe, z0)));
                diag = add4(diag, add4(zsm(pn4, z0), zsp(pn4, z0)));
                diag = add4(diag, add4(zsm(ps4, z0), zsp(ps4, z0)));
            }

            // A^2 p: center coeff = 42 - n_out (per component for z)
            float cm = 42.f - (float)((!w1) + (!e1) + (!n1) + (!s1));
            float cx = cm - (z0 == 0  ? 1.f : 0.f);
            float cw = cm - (z0 == 60 ? 1.f : 0.f);
            float4 a2;
            a2.x = cx * pc.x - 12.f * S1.x + ax2.x + 2.f * diag.x;
            a2.y = cm * pc.y - 12.f * S1.y + ax2.y + 2.f * diag.y;
            a2.z = cm * pc.z - 12.f * S1.z + ax2.z + 2.f * diag.z;
            a2.w = cw * pc.w - 12.f * S1.w + ax2.w + 2.f * diag.w;

            // r_{k-1} = p_{k-1} - beta_{k-1} p_{k-2}; A r likewise
            float4 rc, arc;
            if (k == 1) {
                rc = pc; arc = ap;
            } else {
                float4 qc  = ld4(qq + i);
                float4 qw  = w1 ? ld4(qq + i - Zq) : Zv;
                float4 qe  = e1 ? ld4(qq + i + Zq) : Zv;
                float4 qn4 = n1 ? ld4(qq + i - WZ) : Zv;
                float4 qs4 = s1 ? ld4(qq + i + WZ) : Zv;
                float4 aq = lap(qc, qw, qe, qn4, qs4, z0);
                rc  = make_float4(pc.x - bp * qc.x,  pc.y - bp * qc.y,
                                  pc.z - bp * qc.z,  pc.w - bp * qc.w);
                arc = make_float4(ap.x - bp * aq.x, ap.y - bp * aq.y,
                                  ap.z - bp * aq.z, ap.w - bp * aq.w);
            }

            // r_k = r_{k-1} - alpha A p_{k-1}
            float4 rk = make_float4(rc.x - al * ap.x, rc.y - al * ap.y,
                                    rc.z - al * ap.z, rc.w - al * ap.w);
            accR += dot4(rk, rk);
            // A r_k = A r_{k-1} - alpha A^2 p_{k-1}
            float4 ark = make_float4(arc.x - al * a2.x, arc.y - al * a2.y,
                                     arc.z - al * a2.z, arc.w - al * a2.w);
            // p_k = r_k + beta_k p_{k-1}
            float4 pk = make_float4(rk.x + bk * pc.x, rk.y + bk * pc.y,
                                    rk.z + bk * pc.z, rk.w + bk * pc.w);
            st4(pout + i, pk);
            // w_k = A r_k + beta_k A p_{k-1}
            float4 wk = make_float4(ark.x + bk * ap.x, ark.y + bk * ap.y,
                                    ark.z + bk * ap.z, ark.w + bk * ap.w);
            accE += dot4(pk, wk);
            accT += dot4(rk, wk);
            accO += dot4(wk, wk);
        }
        block_reduce4(accR, accE, accT, accO,
                      &g_rho[k][sb], &g_eta[k][sb],
                      &g_tau[k][sb], &g_om[k][sb]);
        grid_sync();
    }

    // ---- final (desc): r8 via r7 = p7 - b7 p6 ; x = x0 + sum a_k p_k ----
    {
        __shared__ float s_alpha[ITER], s_b7;
        if (threadIdx.x < ITER)
            s_alpha[threadIdx.x] =
                (float)(__ldcg(&g_rho[threadIdx.x][sb]) /
                        (__ldcg(&g_eta[threadIdx.x][sb]) + EPS));
        if (threadIdx.x == 0) {
            double a6, b7;
            scal_ab(ITER - 2, sb, a6, b7);
            s_b7 = (float)b7;
        }
        __syncthreads();
        const float a7 = s_alpha[ITER - 1], b7 = s_b7;

        float accR = 0.f, accL = 0.f, mx = 0.f;
        for (int t = sblk; t < TPS; t += SBLK) {
            int tt = TPS - 1 - t;
            int i, z0, wi, h; decode(sb, tt, i, z0, wi, h);
            bool w1 = wi > 0, e1 = wi < Wq - 1, n1 = h > 0, s1 = h < Hq - 1;
            const float* p7 = g_p[ITER - 1];
            float4 pc  = ld4(p7 + i);
            float4 pw  = w1 ? ld4(p7 + i - Zq) : Zv;
            float4 pe  = e1 ? ld4(p7 + i + Zq) : Zv;
            float4 pn4 = n1 ? ld4(p7 + i - WZ) : Zv;
            float4 ps4 = s1 ? ld4(p7 + i + WZ) : Zv;
            float4 w7 = lap(pc, pw, pe, pn4, ps4, z0);

            float4 x = ld4cs(x0 + i);
            float4 p6c;
            #pragma unroll
            for (int k = 0; k < ITER - 1; ++k) {
                float a = s_alpha[k];
                float4 pk = ld4cs(g_p[k] + i);
                if (k == ITER - 2) p6c = pk;
                x.x += a * pk.x; x.y += a * pk.y;
                x.z += a * pk.z; x.w += a * pk.w;
            }
            x.x += a7 * pc.x; x.y += a7 * pc.y;
            x.z += a7 * pc.z; x.w += a7 * pc.w;

            float4 r8 = make_float4(pc.x - b7 * p6c.x - a7 * w7.x,
                                    pc.y - b7 * p6c.y - a7 * w7.y,
                                    pc.z - b7 * p6c.z - a7 * w7.z,
                                    pc.w - b7 * p6c.w - a7 * w7.w);
            accR += dot4(r8, r8);

            __stcs(out + 1 + i + 0, x.x);
            __stcs(out + 1 + i + 1, x.y);
            __stcs(out + 1 + i + 2, x.z);
            __stcs(out + 1 + i + 3, x.w);

            float4 rf = ld4cs(ref + i);
            float dx = x.x - rf.x, dy = x.y - rf.y;
            float dz = x.z - rf.z, dw = x.w - rf.w;
            accL += dx * dx + dy * dy + dz * dz + dw * dw;
            mx = fmaxf(mx, fmaxf(fmaxf(fabsf(dx), fabsf(dy)),
                                 fmaxf(fabsf(dz), fabsf(dw))));
        }
        block_reduce_add(accR, &g_rho[ITER][sb]);
        block_reduce_add(accL, &g_loss);
        block_reduce_max(mx, &g_max);
    }
}

__global__ void k_writeout(float* __restrict__ out) {
    out[0] = (float)(g_loss / (double)N);
    out[N + 1] = __uint_as_float(g_max);
    double s = 0.0;
    #pragma unroll
    for (int b = 0; b < Bq; ++b) s += g_rho[ITER][b];
    out[N + 2] = (float)(s / (double)Bq);
}

// ---------------------------------------------------------------------------

extern "C" void kernel_launch(void* const* d_in, const int* in_sizes, int n_in,
                              void* d_out, int out_size) {
    const float* x   = (const float*)d_in[0];
    const float* b   = (const float*)d_in[1];
    const float* ref = (const float*)d_in[2];
    float* out = (float*)d_out;

    k_zero<<<1, 64>>>();
    k_cg<<<GRID, NT>>>(x, b, ref, out);
    k_writeout<<<1, 1>>>(out);
}

// round 13
// speedup vs baseline: 1.0377x; 1.0377x over previous
#include <cuda_runtime.h>

// Problem constants
#define Bq 4
#define Hq 256
#define Wq 256
#define Zq 64
#define ITER 8
#define EPS 1e-6

constexpr int N    = Bq * Hq * Wq * Zq;   // 16,777,216
constexpr int SAMP = Hq * Wq * Zq;        // 4,194,304
#define NT 256
constexpr int OCC  = 5;
constexpr int GRID = 148 * OCC;           // 740 blocks, co-resident
constexpr int SBLK = GRID / Bq;           // 185 blocks per sample
constexpr int TPS  = SAMP / (NT * 4);     // 4096 tiles per sample
constexpr int WZ   = Wq * Zq;

// Scratch (device globals; allocation forbidden). Write-once versioning:
// each r_k / w_k array is written exactly once, read only after -> no
// stale-L1 hazard across phases of the persistent kernel.
__device__ float g_r[ITER][N];   // r_0..r_7
__device__ float g_w[ITER][N];   // w_k = A p_k

__device__ double   g_rho[ITER][Bq];   // direct r_k.r_k
__device__ double   g_tau[ITER][Bq];   // r_k.w_k
__device__ double   g_sig[ITER][Bq];   // r_k.w_{k-1}   (sig[0] unused)
__device__ double   g_om [ITER][Bq];   // w_k.w_k
__device__ double   g_loss;
__device__ unsigned g_max;

__device__ unsigned g_bar_count;
__device__ unsigned g_bar_gen;

// ---------------------------------------------------------------------------
// helpers
// ---------------------------------------------------------------------------

__device__ __forceinline__ float4 ld4(const float* __restrict__ p) {
    return *reinterpret_cast<const float4*>(p);
}
__device__ __forceinline__ float4 ld4cs(const float* __restrict__ p) {
    return __ldcs(reinterpret_cast<const float4*>(p));
}
__device__ __forceinline__ void st4(float* __restrict__ p, float4 v) {
    *reinterpret_cast<float4*>(p) = v;
}
__device__ __forceinline__ float dot4(float4 a, float4 b) {
    return a.x * b.x + a.y * b.y + a.z * b.z + a.w * b.w;
}

// 7-pt Laplacian; z-neighbors via lane shuffle (16 lanes tile one z-line;
// lane-boundary shuffles masked by z0). Call from ALL lanes.
__device__ __forceinline__ float4 lap(float4 c, float4 xm, float4 xp,
                                      float4 ym, float4 yp, int z0) {
    float zl = __shfl_up_sync(0xffffffffu, c.w, 1);
    float zr = __shfl_down_sync(0xffffffffu, c.x, 1);
    if (z0 == 0)  zl = 0.f;
    if (z0 == 60) zr = 0.f;
    float4 o;
    o.x = 6.f * c.x - xm.x - xp.x - ym.x - yp.x - zl  - c.y;
    o.y = 6.f * c.y - xm.y - xp.y - ym.y - yp.y - c.x - c.z;
    o.z = 6.f * c.z - xm.z - xp.z - ym.z - yp.z - c.y - c.w;
    o.w = 6.f * c.w - xm.w - xp.w - ym.w - yp.w - c.z - zr;
    return o;
}

// load 7-pt neighborhood of arr and return lap; center returned via *cen
__device__ __forceinline__ float4 lap_of(const float* __restrict__ arr,
                                         int i, int z0, bool w1, bool e1,
                                         bool n1, bool s1, float4* cen) {
    const float4 Zv = make_float4(0.f, 0.f, 0.f, 0.f);
    float4 c  = ld4(arr + i);
    float4 xm = w1 ? ld4(arr + i - Zq) : Zv;
    float4 xp = e1 ? ld4(arr + i + Zq) : Zv;
    float4 ym = n1 ? ld4(arr + i - WZ) : Zv;
    float4 yp = s1 ? ld4(arr + i + WZ) : Zv;
    *cen = c;
    return lap(c, xm, xp, ym, yp, z0);
}

__device__ __forceinline__ void block_reduce_add(float val, double* target) {
    __syncthreads();
    #pragma unroll
    for (int o = 16; o; o >>= 1)
        val += __shfl_xor_sync(0xffffffffu, val, o);
    __shared__ double sh[NT / 32];
    int lane = threadIdx.x & 31, wid = threadIdx.x >> 5;
    if (lane == 0) sh[wid] = (double)val;
    __syncthreads();
    if (threadIdx.x == 0) {
        double s = 0.0;
        #pragma unroll
        for (int k = 0; k < NT / 32; ++k) s += sh[k];
        atomicAdd(target, s);
    }
}

__device__ __forceinline__ void block_reduce4(float v0, float v1, float v2,
                                              float v3, double* t0, double* t1,
                                              double* t2, double* t3) {
    __syncthreads();
    #pragma unroll
    for (int o = 16; o; o >>= 1) {
        v0 += __shfl_xor_sync(0xffffffffu, v0, o);
        v1 += __shfl_xor_sync(0xffffffffu, v1, o);
        v2 += __shfl_xor_sync(0xffffffffu, v2, o);
        v3 += __shfl_xor_sync(0xffffffffu, v3, o);
    }
    __shared__ double sh[4][NT / 32];
    int lane = threadIdx.x & 31, wid = threadIdx.x >> 5;
    if (lane == 0) {
        sh[0][wid] = v0; sh[1][wid] = v1; sh[2][wid] = v2; sh[3][wid] = v3;
    }
    __syncthreads();
    if (threadIdx.x < 4) {
        double s = 0.0;
        #pragma unroll
        for (int k = 0; k < NT / 32; ++k) s += sh[threadIdx.x][k];
        double* tgt = (threadIdx.x == 0) ? t0 : (threadIdx.x == 1) ? t1
                    : (threadIdx.x == 2) ? t2 : t3;
        atomicAdd(tgt, s);
    }
}

__device__ __forceinline__ void block_reduce_max(float val, unsigned* target) {
    __syncthreads();
    #pragma unroll
    for (int o = 16; o; o >>= 1)
        val = fmaxf(val, __shfl_xor_sync(0xffffffffu, val, o));
    __shared__ float shm[NT / 32];
    int lane = threadIdx.x & 31, wid = threadIdx.x >> 5;
    if (lane == 0) shm[wid] = val;
    __syncthreads();
    if (threadIdx.x == 0) {
        float m = 0.f;
        #pragma unroll
        for (int k = 0; k < NT / 32; ++k) m = fmaxf(m, shm[k]);
        atomicMax(target, __float_as_uint(m));
    }
}

__device__ __forceinline__ void grid_sync() {
    __syncthreads();
    if (threadIdx.x == 0) {
        unsigned my = *(volatile unsigned*)&g_bar_gen;
        __threadfence();
        if (atomicAdd(&g_bar_count, 1) == GRID - 1) {
            g_bar_count = 0;
            __threadfence();
            atomicAdd(&g_bar_gen, 1);
        } else {
            while (*(volatile unsigned*)&g_bar_gen == my) __nanosleep(64);
        }
        __threadfence();
    }
    __syncthreads();
}

__device__ __forceinline__ void decode(int sb, int t, int& i, int& z0,
                                       int& wi, int& h) {
    i  = (sb << 22) + (t * NT + (int)threadIdx.x) * 4;
    z0 = i & 63;
    wi = (i >> 6) & 255;
    h  = (i >> 14) & 255;
}

// Scalar replay (double, fixed op order — deterministic on every block):
// produces alpha_{k-1} and beta_k from the stored dot arrays.
//   eta_0 = tau_0
//   alpha_j = rho_j / (eta_j + EPS)
//   beta_{j+1} = (rho_j - 2 a tau_j + a^2 om_j) / (rho_j + EPS)
//   eta_{j+1} = tau_{j+1} + b sig_{j+1} + b^2 eta_j
__device__ __forceinline__ void replay(int k, int sb, double& al, double& bt) {
    double eta = __ldcg(&g_tau[0][sb]);
    al = 0.0; bt = 0.0;
    for (int j = 1; j <= k; ++j) {
        double r = __ldcg(&g_rho[j - 1][sb]);
        double t = __ldcg(&g_tau[j - 1][sb]);
        double o = __ldcg(&g_om [j - 1][sb]);
        al = r / (eta + EPS);                          // alpha_{j-1}
        double rr = r - 2.0 * al * t + al * al * o;
        bt = rr / (r + EPS);                           // beta_j
        if (j < k) {
            double tj = __ldcg(&g_tau[j][sb]);
            double sj = __ldcg(&g_sig[j][sb]);
            eta = tj + bt * sj + bt * bt * eta;        // eta_j
        }
    }
}

// ---------------------------------------------------------------------------
// kernels
// ---------------------------------------------------------------------------

__global__ void k_zero() {
    int t = threadIdx.x;
    if (t < ITER * Bq) {
        ((double*)g_rho)[t] = 0.0;
        ((double*)g_tau)[t] = 0.0;
        ((double*)g_sig)[t] = 0.0;
        ((double*)g_om)[t]  = 0.0;
    }
    if (t == 0) { g_loss = 0.0; g_max = 0u; }
}

__global__ void __launch_bounds__(NT, OCC)
k_cg(const float* __restrict__ x0, const float* __restrict__ bin,
     const float* __restrict__ ref, float* __restrict__ out) {
    const int sb   = (int)blockIdx.x & 3;
    const int sblk = (int)blockIdx.x >> 2;
    __shared__ float s_a, s_b;

    // ---- P0 (asc): r0 = b - A x0 ; rho0 ----
    {
        float acc = 0.f;
        for (int t = sblk; t < TPS; t += SBLK) {
            int i, z0, wi, h; decode(sb, t, i, z0, wi, h);
            float4 xc;
            float4 ax = lap_of(x0, i, z0, wi > 0, wi < Wq - 1,
                               h > 0, h < Hq - 1, &xc);
            float4 bb = ld4cs(bin + i);
            float4 r0 = make_float4(bb.x - ax.x, bb.y - ax.y,
                                    bb.z - ax.z, bb.w - ax.w);
            st4(g_r[0] + i, r0);
            acc += dot4(r0, r0);
        }
        block_reduce_add(acc, &g_rho[0][sb]);
    }
    grid_sync();

    // ---- P1 (desc): w0 = A r0 (store) ; tau0 = r0.w0 ; om0 = w0.w0 ----
    {
        float accT = 0.f, accO = 0.f;
        for (int t = sblk; t < TPS; t += SBLK) {
            int tt = TPS - 1 - t;
            int i, z0, wi, h; decode(sb, tt, i, z0, wi, h);
            float4 rc;
            float4 w = lap_of(g_r[0], i, z0, wi > 0, wi < Wq - 1,
                              h > 0, h < Hq - 1, &rc);
            st4(g_w[0] + i, w);
            accT += dot4(rc, w);
            accO += dot4(w, w);
        }
        block_reduce4(accT, accO, 0.f, 0.f,
                      &g_tau[0][sb], &g_om[0][sb],
                      &g_sig[0][sb], &g_sig[0][sb]);
    }
    grid_sync();

    // ---- phases k = 1..7: two 7-pt stencils (r,w), one CG iter each ----
    for (int k = 1; k < ITER; ++k) {
        if (threadIdx.x == 0) {
            double al, bt;
            replay(k, sb, al, bt);      // alpha_{k-1}, beta_k
            s_a = (float)al;
            s_b = (float)bt;
        }
        __syncthreads();
        const float al = s_a, bk = s_b;
        const float* rin = g_r[k - 1];
        const float* win = g_w[k - 1];
        float* rout = g_r[k];
        float* wout = g_w[k];
        const bool rev = !(k & 1);
        float accR = 0.f, accT = 0.f, accS = 0.f, accO = 0.f;

        for (int t = sblk; t < TPS; t += SBLK) {
            int tt = rev ? TPS - 1 - t : t;
            int i, z0, wi, h; decode(sb, tt, i, z0, wi, h);
            bool w1 = wi > 0, e1 = wi < Wq - 1, n1 = h > 0, s1 = h < Hq - 1;

            float4 rc, wc;
            float4 lr = lap_of(rin, i, z0, w1, e1, n1, s1, &rc);  // A r_{k-1}
            float4 lw = lap_of(win, i, z0, w1, e1, n1, s1, &wc);  // A w_{k-1}

            // r_k = r_{k-1} - alpha w_{k-1}
            float4 rk = make_float4(rc.x - al * wc.x, rc.y - al * wc.y,
                                    rc.z - al * wc.z, rc.w - al * wc.w);
            st4(rout + i, rk);
            // A r_k = A r_{k-1} - alpha A w_{k-1}
            float4 ark = make_float4(lr.x - al * lw.x, lr.y - al * lw.y,
                                     lr.z - al * lw.z, lr.w - al * lw.w);
            // w_k = A r_k + beta_k w_{k-1}
            float4 wk = make_float4(ark.x + bk * wc.x, ark.y + bk * wc.y,
                                    ark.z + bk * wc.z, ark.w + bk * wc.w);
            st4(wout + i, wk);

            accR += dot4(rk, rk);       // rho_k (direct)
            accT += dot4(rk, wk);       // tau_k
            accS += dot4(rk, wc);       // sig_k
            accO += dot4(wk, wk);       // om_k
        }
        block_reduce4(accR, accT, accS, accO,
                      &g_rho[k][sb], &g_tau[k][sb],
                      &g_sig[k][sb], &g_om[k][sb]);
        grid_sync();
    }

    // ---- final (desc): x = x0 + sum_j c_j r_j ; out / loss / max ----
    // c_7 = alpha_7 ; c_j = alpha_j + beta_{j+1} c_{j+1}
    {
        __shared__ float s_c[ITER];
        if (threadIdx.x == 0) {
            double alpha[ITER], beta[ITER];
            double eta = __ldcg(&g_tau[0][sb]);
            for (int j = 0; j < ITER; ++j) {
                double r = __ldcg(&g_rho[j][sb]);
                double a = r / (eta + EPS);
                alpha[j] = a;
                if (j < ITER - 1) {
                    double t = __ldcg(&g_tau[j][sb]);
                    double o = __ldcg(&g_om[j][sb]);
                    double rr = r - 2.0 * a * t + a * a * o;
                    double b = rr / (r + EPS);
                    beta[j + 1] = b;
                    double tj = __ldcg(&g_tau[j + 1][sb]);
                    double sj = __ldcg(&g_sig[j + 1][sb]);
                    eta = tj + b * sj + b * b * eta;
                }
            }
            double c = alpha[ITER - 1];
            s_c[ITER - 1] = (float)c;
            for (int j = ITER - 2; j >= 0; --j) {
                c = alpha[j] + beta[j + 1] * c;
                s_c[j] = (float)c;
            }
        }
        __syncthreads();

        float accL = 0.f, mx = 0.f;
        for (int t = sblk; t < TPS; t += SBLK) {
            int tt = TPS - 1 - t;
            int i, z0, wi, h; decode(sb, tt, i, z0, wi, h);
            float4 x = ld4cs(x0 + i);
            #pragma unroll
            for (int k = 0; k < ITER; ++k) {
                float c = s_c[k];
                float4 rk = ld4cs(g_r[k] + i);
                x.x += c * rk.x; x.y += c * rk.y;
                x.z += c * rk.z; x.w += c * rk.w;
            }
            __stcs(out + 1 + i + 0, x.x);
            __stcs(out + 1 + i + 1, x.y);
            __stcs(out + 1 + i + 2, x.z);
            __stcs(out + 1 + i + 3, x.w);

            float4 rf = ld4cs(ref + i);
            float dx = x.x - rf.x, dy = x.y - rf.y;
            float dz = x.z - rf.z, dw = x.w - rf.w;
            accL += dx * dx + dy * dy + dz * dz + dw * dw;
            mx = fmaxf(mx, fmaxf(fmaxf(fabsf(dx), fabsf(dy)),
                                 fmaxf(fabsf(dz), fabsf(dw))));
        }
        block_reduce_add(accL, &g_loss);
        block_reduce_max(mx, &g_max);
    }
}

__global__ void k_writeout(float* __restrict__ out) {
    out[0] = (float)(g_loss / (double)N);
    out[N + 1] = __uint_as_float(g_max);
    // rho_8 per sample via the same scalar replay + one recurrence step
    double s = 0.0;
    for (int sb = 0; sb < Bq; ++sb) {
        double eta = g_tau[0][sb];
        double rho8 = 0.0;
        for (int j = 0; j < ITER; ++j) {
            double r = g_rho[j][sb];
            double a = r / (eta + EPS);
            double t = g_tau[j][sb];
            double o = g_om[j][sb];
            double rr = r - 2.0 * a * t + a * a * o;
            if (j == ITER - 1) { rho8 = rr; break; }
            double b = rr / (r + EPS);
            double tj = g_tau[j + 1][sb];
            double sj = g_sig[j + 1][sb];
            eta = tj + b * sj + b * b * eta;
        }
        s += rho8;
    }
    out[N + 2] = (float)(s / (double)Bq);
}

// ---------------------------------------------------------------------------

extern "C" void kernel_launch(void* const* d_in, const int* in_sizes, int n_in,
                              void* d_out, int out_size) {
    const float* x   = (const float*)d_in[0];
    const float* b   = (const float*)d_in[1];
    const float* ref = (const float*)d_in[2];
    float* out = (float*)d_out;

    k_zero<<<1, 64>>>();
    k_cg<<<GRID, NT>>>(x, b, ref, out);
    k_writeout<<<1, 1>>>(out);
}

// round 14
// speedup vs baseline: 1.0568x; 1.0184x over previous
#include <cuda_runtime.h>

// Problem constants
#define Bq 4
#define Hq 256
#define Wq 256
#define Zq 64
#define ITER 8
#define EPS 1e-6

constexpr int N    = Bq * Hq * Wq * Zq;   // 16,777,216
constexpr int SAMP = Hq * Wq * Zq;        // 4,194,304
#define NT 256
constexpr int OCC  = 5;
constexpr int GRID = 148 * OCC;           // 740 blocks, co-resident
constexpr int SBLK = GRID / Bq;           // 185 blocks per sample
constexpr int TPS  = SAMP / (NT * 4);     // 4096 tiles per sample
constexpr int WZ   = Wq * Zq;

// Scratch (device globals; allocation forbidden). Write-once versioning:
// each r_k / w_k array is written exactly once, read only after -> no
// stale-L1 hazard across phases of the persistent kernel.
__device__ float g_r[ITER][N];        // r_0..r_7
__device__ float g_w[ITER - 1][N];    // w_0..w_6 (w_7 never stored)

__device__ double   g_rho[ITER][Bq];  // direct r_k.r_k
__device__ double   g_tau[ITER][Bq];  // r_k.w_k
__device__ double   g_sig[ITER][Bq];  // r_k.w_{k-1}  (sig[0] unused)
__device__ double   g_om [ITER][Bq];  // w_k.w_k
__device__ double   g_loss;
__device__ unsigned g_max;

// per-sample barriers (count self-resets; gen monotonic across replays)
__device__ unsigned g_bar_count[Bq];
__device__ unsigned g_bar_gen[Bq];

// ---------------------------------------------------------------------------
// helpers
// ---------------------------------------------------------------------------

__device__ __forceinline__ float4 ld4(const float* __restrict__ p) {
    return *reinterpret_cast<const float4*>(p);
}
__device__ __forceinline__ float4 ld4cs(const float* __restrict__ p) {
    return __ldcs(reinterpret_cast<const float4*>(p));
}
__device__ __forceinline__ void st4(float* __restrict__ p, float4 v) {
    *reinterpret_cast<float4*>(p) = v;
}
__device__ __forceinline__ float dot4(float4 a, float4 b) {
    return a.x * b.x + a.y * b.y + a.z * b.z + a.w * b.w;
}

// 7-pt Laplacian; z-neighbors via lane shuffle (16 lanes tile one z-line;
// lane-boundary shuffles masked by z0). Call from ALL lanes.
__device__ __forceinline__ float4 lap(float4 c, float4 xm, float4 xp,
                                      float4 ym, float4 yp, int z0) {
    float zl = __shfl_up_sync(0xffffffffu, c.w, 1);
    float zr = __shfl_down_sync(0xffffffffu, c.x, 1);
    if (z0 == 0)  zl = 0.f;
    if (z0 == 60) zr = 0.f;
    float4 o;
    o.x = 6.f * c.x - xm.x - xp.x - ym.x - yp.x - zl  - c.y;
    o.y = 6.f * c.y - xm.y - xp.y - ym.y - yp.y - c.x - c.z;
    o.z = 6.f * c.z - xm.z - xp.z - ym.z - yp.z - c.y - c.w;
    o.w = 6.f * c.w - xm.w - xp.w - ym.w - yp.w - c.z - zr;
    return o;
}

// load 7-pt neighborhood of arr and return lap; center via *cen
__device__ __forceinline__ float4 lap_of(const float* __restrict__ arr,
                                         int i, int z0, bool w1, bool e1,
                                         bool n1, bool s1, float4* cen) {
    const float4 Zv = make_float4(0.f, 0.f, 0.f, 0.f);
    float4 c  = ld4(arr + i);
    float4 xm = w1 ? ld4(arr + i - Zq) : Zv;
    float4 xp = e1 ? ld4(arr + i + Zq) : Zv;
    float4 ym = n1 ? ld4(arr + i - WZ) : Zv;
    float4 yp = s1 ? ld4(arr + i + WZ) : Zv;
    *cen = c;
    return lap(c, xm, xp, ym, yp, z0);
}

__device__ __forceinline__ void block_reduce_add(float val, double* target) {
    __syncthreads();
    #pragma unroll
    for (int o = 16; o; o >>= 1)
        val += __shfl_xor_sync(0xffffffffu, val, o);
    __shared__ double sh[NT / 32];
    int lane = threadIdx.x & 31, wid = threadIdx.x >> 5;
    if (lane == 0) sh[wid] = (double)val;
    __syncthreads();
    if (threadIdx.x == 0) {
        double s = 0.0;
        #pragma unroll
        for (int k = 0; k < NT / 32; ++k) s += sh[k];
        atomicAdd(target, s);
    }
}

__device__ __forceinline__ void block_reduce4(float v0, float v1, float v2,
                                              float v3, double* t0, double* t1,
                                              double* t2, double* t3) {
    __syncthreads();
    #pragma unroll
    for (int o = 16; o; o >>= 1) {
        v0 += __shfl_xor_sync(0xffffffffu, v0, o);
        v1 += __shfl_xor_sync(0xffffffffu, v1, o);
        v2 += __shfl_xor_sync(0xffffffffu, v2, o);
        v3 += __shfl_xor_sync(0xffffffffu, v3, o);
    }
    __shared__ double sh[4][NT / 32];
    int lane = threadIdx.x & 31, wid = threadIdx.x >> 5;
    if (lane == 0) {
        sh[0][wid] = v0; sh[1][wid] = v1; sh[2][wid] = v2; sh[3][wid] = v3;
    }
    __syncthreads();
    if (threadIdx.x < 4) {
        double s = 0.0;
        #pragma unroll
        for (int k = 0; k < NT / 32; ++k) s += sh[threadIdx.x][k];
        double* tgt = (threadIdx.x == 0) ? t0 : (threadIdx.x == 1) ? t1
                    : (threadIdx.x == 2) ? t2 : t3;
        atomicAdd(tgt, s);
    }
}

__device__ __forceinline__ void block_reduce_max(float val, unsigned* target) {
    __syncthreads();
    #pragma unroll
    for (int o = 16; o; o >>= 1)
        val = fmaxf(val, __shfl_xor_sync(0xffffffffu, val, o));
    __shared__ float shm[NT / 32];
    int lane = threadIdx.x & 31, wid = threadIdx.x >> 5;
    if (lane == 0) shm[wid] = val;
    __syncthreads();
    if (threadIdx.x == 0) {
        float m = 0.f;
        #pragma unroll
        for (int k = 0; k < NT / 32; ++k) m = fmaxf(m, shm[k]);
        atomicMax(target, __float_as_uint(m));
    }
}

// per-sample grid barrier: only the SBLK blocks of sample sb participate.
__device__ __forceinline__ void sample_sync(int sb) {
    __syncthreads();
    if (threadIdx.x == 0) {
        unsigned my = *(volatile unsigned*)&g_bar_gen[sb];   // read BEFORE arrive
        __threadfence();
        if (atomicAdd(&g_bar_count[sb], 1) == SBLK - 1) {
            g_bar_count[sb] = 0;
            __threadfence();
            atomicAdd(&g_bar_gen[sb], 1);
        } else {
            while (*(volatile unsigned*)&g_bar_gen[sb] == my) __nanosleep(64);
        }
        __threadfence();
    }
    __syncthreads();
}

__device__ __forceinline__ void decode(int sb, int t, int& i, int& z0,
                                       int& wi, int& h) {
    i  = (sb << 22) + (t * NT + (int)threadIdx.x) * 4;
    z0 = i & 63;
    wi = (i >> 6) & 255;
    h  = (i >> 14) & 255;
}

// Scalar replay (double, fixed op order — deterministic on every block):
// alpha_{k-1} and beta_k from the stored dot arrays.
//   eta_0 = tau_0; alpha_j = rho_j/(eta_j+EPS)
//   beta_{j+1} = (rho_j - 2 a tau_j + a^2 om_j)/(rho_j+EPS)
//   eta_{j+1} = tau_{j+1} + b sig_{j+1} + b^2 eta_j
__device__ __forceinline__ void replay(int k, int sb, double& al, double& bt) {
    double eta = __ldcg(&g_tau[0][sb]);
    al = 0.0; bt = 0.0;
    for (int j = 1; j <= k; ++j) {
        double r = __ldcg(&g_rho[j - 1][sb]);
        double t = __ldcg(&g_tau[j - 1][sb]);
        double o = __ldcg(&g_om [j - 1][sb]);
        al = r / (eta + EPS);
        double rr = r - 2.0 * al * t + al * al * o;
        bt = rr / (r + EPS);
        if (j < k) {
            double tj = __ldcg(&g_tau[j][sb]);
            double sj = __ldcg(&g_sig[j][sb]);
            eta = tj + bt * sj + bt * bt * eta;
        }
    }
}

// ---------------------------------------------------------------------------
// kernels
// ---------------------------------------------------------------------------

__global__ void k_zero() {
    int t = threadIdx.x;
    if (t < ITER * Bq) {
        ((double*)g_rho)[t] = 0.0;
        ((double*)g_tau)[t] = 0.0;
        ((double*)g_sig)[t] = 0.0;
        ((double*)g_om)[t]  = 0.0;
    }
    if (t == 0) { g_loss = 0.0; g_max = 0u; }
}

__global__ void __launch_bounds__(NT, OCC)
k_cg(const float* __restrict__ x0, const float* __restrict__ bin,
     const float* __restrict__ ref, float* __restrict__ out) {
    const int sb   = (int)blockIdx.x & 3;
    const int sblk = (int)blockIdx.x >> 2;
    __shared__ float s_a, s_b;

    // ---- P0 (asc): r0 = b - A x0 ; rho0 ----
    {
        float acc = 0.f;
        for (int t = sblk; t < TPS; t += SBLK) {
            int i, z0, wi, h; decode(sb, t, i, z0, wi, h);
            float4 xc;
            float4 ax = lap_of(x0, i, z0, wi > 0, wi < Wq - 1,
                               h > 0, h < Hq - 1, &xc);
            float4 bb = ld4cs(bin + i);
            float4 r0 = make_float4(bb.x - ax.x, bb.y - ax.y,
                                    bb.z - ax.z, bb.w - ax.w);
            st4(g_r[0] + i, r0);
            acc += dot4(r0, r0);
        }
        block_reduce_add(acc, &g_rho[0][sb]);
    }
    sample_sync(sb);

    // ---- P1 (desc): w0 = A r0 (store) ; tau0 = r0.w0 ; om0 = w0.w0 ----
    {
        float accT = 0.f, accO = 0.f;
        for (int t = sblk; t < TPS; t += SBLK) {
            int tt = TPS - 1 - t;
            int i, z0, wi, h; decode(sb, tt, i, z0, wi, h);
            float4 rc;
            float4 w = lap_of(g_r[0], i, z0, wi > 0, wi < Wq - 1,
                              h > 0, h < Hq - 1, &rc);
            st4(g_w[0] + i, w);
            accT += dot4(rc, w);
            accO += dot4(w, w);
        }
        block_reduce4(accT, accO, 0.f, 0.f,
                      &g_tau[0][sb], &g_om[0][sb],
                      &g_sig[0][sb], &g_sig[0][sb]);
    }
    sample_sync(sb);

    // ---- phases k = 1..7: two 7-pt stencils (r,w), one CG iter each ----
    for (int k = 1; k < ITER; ++k) {
        if (threadIdx.x == 0) {
            double al, bt;
            replay(k, sb, al, bt);      // alpha_{k-1}, beta_k
            s_a = (float)al;
            s_b = (float)bt;
        }
        __syncthreads();
        const float al = s_a, bk = s_b;
        const float* rin = g_r[k - 1];
        const float* win = g_w[k - 1];
        float* rout = g_r[k];
        float* wout = (k < ITER - 1) ? g_w[k] : nullptr;
        const bool storeW = (k < ITER - 1);   // w_7 never needed
        const bool rev = !(k & 1);
        float accR = 0.f, accT = 0.f, accS = 0.f, accO = 0.f;

        for (int t = sblk; t < TPS; t += SBLK) {
            int tt = rev ? TPS - 1 - t : t;
            int i, z0, wi, h; decode(sb, tt, i, z0, wi, h);
            bool w1 = wi > 0, e1 = wi < Wq - 1, n1 = h > 0, s1 = h < Hq - 1;

            float4 rc, wc;
            float4 lr = lap_of(rin, i, z0, w1, e1, n1, s1, &rc);  // A r_{k-1}
            float4 lw = lap_of(win, i, z0, w1, e1, n1, s1, &wc);  // A w_{k-1}

            // r_k = r_{k-1} - alpha w_{k-1}
            float4 rk = make_float4(rc.x - al * wc.x, rc.y - al * wc.y,
                                    rc.z - al * wc.z, rc.w - al * wc.w);
            st4(rout + i, rk);
            // A r_k = A r_{k-1} - alpha A w_{k-1}
            float4 ark = make_float4(lr.x - al * lw.x, lr.y - al * lw.y,
                                     lr.z - al * lw.z, lr.w - al * lw.w);
            // w_k = A r_k + beta_k w_{k-1}
            float4 wk = make_float4(ark.x + bk * wc.x, ark.y + bk * wc.y,
                                    ark.z + bk * wc.z, ark.w + bk * wc.w);
            if (storeW) st4(wout + i, wk);

            accR += dot4(rk, rk);
            accT += dot4(rk, wk);
            accS += dot4(rk, wc);
            accO += dot4(wk, wk);
        }
        block_reduce4(accR, accT, accS, accO,
                      &g_rho[k][sb], &g_tau[k][sb],
                      &g_sig[k][sb], &g_om[k][sb]);
        sample_sync(sb);
    }

    // ---- final (desc): x = x0 + sum_j c_j r_j ; out / loss / max ----
    // c_7 = alpha_7 ; c_j = alpha_j + beta_{j+1} c_{j+1}
    {
        __shared__ float s_c[ITER];
        if (threadIdx.x == 0) {
            double alpha[ITER], beta[ITER];
            double eta = __ldcg(&g_tau[0][sb]);
            for (int j = 0; j < ITER; ++j) {
                double r = __ldcg(&g_rho[j][sb]);
                double a = r / (eta + EPS);
                alpha[j] = a;
                if (j < ITER - 1) {
                    double t = __ldcg(&g_tau[j][sb]);
                    double o = __ldcg(&g_om[j][sb]);
                    double rr = r - 2.0 * a * t + a * a * o;
                    double b = rr / (r + EPS);
                    beta[j + 1] = b;
                    double tj = __ldcg(&g_tau[j + 1][sb]);
                    double sj = __ldcg(&g_sig[j + 1][sb]);
                    eta = tj + b * sj + b * b * eta;
                }
            }
            double c = alpha[ITER - 1];
            s_c[ITER - 1] = (float)c;
            for (int j = ITER - 2; j >= 0; --j) {
                c = alpha[j] + beta[j + 1] * c;
                s_c[j] = (float)c;
            }
        }
        __syncthreads();

        float accL = 0.f, mx = 0.f;
        for (int t = sblk; t < TPS; t += SBLK) {
            int tt = TPS - 1 - t;
            int i, z0, wi, h; decode(sb, tt, i, z0, wi, h);
            float4 x = ld4cs(x0 + i);
            #pragma unroll
            for (int k = 0; k < ITER; ++k) {
                float c = s_c[k];
                float4 rk = ld4cs(g_r[k] + i);
                x.x += c * rk.x; x.y += c * rk.y;
                x.z += c * rk.z; x.w += c * rk.w;
            }
            __stcs(out + 1 + i + 0, x.x);
            __stcs(out + 1 + i + 1, x.y);
            __stcs(out + 1 + i + 2, x.z);
            __stcs(out + 1 + i + 3, x.w);

            float4 rf = ld4cs(ref + i);
            float dx = x.x - rf.x, dy = x.y - rf.y;
            float dz = x.z - rf.z, dw = x.w - rf.w;
            accL += dx * dx + dy * dy + dz * dz + dw * dw;
            mx = fmaxf(mx, fmaxf(fmaxf(fabsf(dx), fabsf(dy)),
                                 fmaxf(fabsf(dz), fabsf(dw))));
        }
        block_reduce_add(accL, &g_loss);
        block_reduce_max(mx, &g_max);
    }
}

__global__ void k_writeout(float* __restrict__ out) {
    out[0] = (float)(g_loss / (double)N);
    out[N + 1] = __uint_as_float(g_max);
    // rho_8 per sample via the same scalar replay + one recurrence step
    double s = 0.0;
    for (int sb = 0; sb < Bq; ++sb) {
        double eta = g_tau[0][sb];
        double rho8 = 0.0;
        for (int j = 0; j < ITER; ++j) {
            double r = g_rho[j][sb];
            double a = r / (eta + EPS);
            double t = g_tau[j][sb];
            double o = g_om[j][sb];
            double rr = r - 2.0 * a * t + a * a * o;
            if (j == ITER - 1) { rho8 = rr; break; }
            double b = rr / (r + EPS);
            double tj = g_tau[j + 1][sb];
            double sj = g_sig[j + 1][sb];
            eta = tj + b * sj + b * b * eta;
        }
        s += rho8;
    }
    out[N + 2] = (float)(s / (double)Bq);
}

// ---------------------------------------------------------------------------

extern "C" void kernel_launch(void* const* d_in, const int* in_sizes, int n_in,
                              void* d_out, int out_size) {
    const float* x   = (const float*)d_in[0];
    const float* b   = (const float*)d_in[1];
    const float* ref = (const float*)d_in[2];
    float* out = (float*)d_out;

    k_zero<<<1, 64>>>();
    k_cg<<<GRID, NT>>>(x, b, ref, out);
    k_writeout<<<1, 1>>>(out);
}